// round 2
// baseline (speedup 1.0000x reference)
#include <cuda_runtime.h>

#define N_NODES 50000
#define N_EDGES 800000
#define D 128
#define NUM_GRAPHS 128
#define N_LAYERS 4
#define BN_EPS 1e-5f

#define BM 64
#define SA_STRIDE 132
#define LAYER_GRID ((N_NODES + BM - 1) / BM)
#define SMEM_FLOATS (16384 + 16384 + BM * SA_STRIDE)
#define SMEM_BYTES (SMEM_FLOATS * 4)

// ---------------- device scratch (no allocations allowed) ----------------
__device__ float g_h[(size_t)N_NODES * D];
__device__ float g_z[(size_t)N_NODES * D];
__device__ int   g_deg[N_NODES];
__device__ int   g_ptr[N_NODES + 1];
__device__ int   g_cursor[N_NODES];
__device__ int   g_csr[N_EDGES];
__device__ float g_stats[(N_LAYERS - 1) * 2 * D];
__device__ int   g_idx64;   // 1 if index buffers are int64, 0 if int32

typedef unsigned long long u64;

__device__ __forceinline__ u64 pack2(float lo, float hi) {
    u64 r;
    asm("mov.b64 %0, {%1, %2};" : "=l"(r) : "f"(lo), "f"(hi));
    return r;
}
__device__ __forceinline__ void unpack2(u64 v, float& lo, float& hi) {
    asm("mov.b64 {%0, %1}, %2;" : "=f"(lo), "=f"(hi) : "l"(v));
}
__device__ __forceinline__ void fma2(u64& d, u64 a, u64 b) {
    asm("fma.rn.f32x2 %0, %1, %2, %0;" : "+l"(d) : "l"(a), "l"(b));
}

__device__ __forceinline__ int load_idx(const void* p, int i) {
    if (g_idx64) return (int)((const long long*)p)[i];
    return ((const int*)p)[i];
}

// ---------------- dtype detection ----------------
// If edge_index is int64 (values < 2^31), every odd int32 word is 0.
__global__ void detect_kernel(const void* ei) {
    __shared__ int any_nonzero;
    const int* a = (const int*)ei;
    if (threadIdx.x == 0) any_nonzero = 0;
    __syncthreads();
    // sample 256 odd int32 positions spread across the int32-view of the buffer
    int step = (2 * N_EDGES) / 256;          // stays within int32-view bounds
    int pos = (threadIdx.x * step) | 1;      // odd position
    if (a[pos] != 0) any_nonzero = 1;
    __syncthreads();
    if (threadIdx.x == 0) g_idx64 = any_nonzero ? 0 : 1;
}

// ---------------- CSR build ----------------
__global__ void zero_kernel(float* __restrict__ out) {
    int i = blockIdx.x * blockDim.x + threadIdx.x;
    int stride = gridDim.x * blockDim.x;
    for (int t = i; t < N_NODES; t += stride) g_deg[t] = 0;
    for (int t = i; t < (N_LAYERS - 1) * 2 * D; t += stride) g_stats[t] = 0.0f;
    for (int t = i; t < NUM_GRAPHS * D; t += stride) out[t] = 0.0f;
}

__global__ void hist_kernel(const void* __restrict__ ei) {
    int e = blockIdx.x * blockDim.x + threadIdx.x;
    if (e < N_EDGES) {
        int dst = load_idx(ei, N_EDGES + e);
        if (dst >= 0 && dst < N_NODES) atomicAdd(&g_deg[dst], 1);
    }
}

__global__ void scan_kernel() {
    __shared__ int wsum[32];
    __shared__ int carry_s;
    const int tid = threadIdx.x;
    const int lane = tid & 31, wid = tid >> 5;
    if (tid == 0) { carry_s = 0; g_ptr[0] = 0; }
    __syncthreads();
    for (int base = 0; base < N_NODES; base += 1024) {
        int idx = base + tid;
        int v = (idx < N_NODES) ? g_deg[idx] : 0;
        int s = v;
        #pragma unroll
        for (int off = 1; off < 32; off <<= 1) {
            int t = __shfl_up_sync(0xffffffffu, s, off);
            if (lane >= off) s += t;
        }
        if (lane == 31) wsum[wid] = s;
        __syncthreads();
        if (wid == 0) {
            int ws = wsum[lane];
            #pragma unroll
            for (int off = 1; off < 32; off <<= 1) {
                int t = __shfl_up_sync(0xffffffffu, ws, off);
                if (lane >= off) ws += t;
            }
            wsum[lane] = ws;
        }
        __syncthreads();
        int incl = s + ((wid > 0) ? wsum[wid - 1] : 0) + carry_s;
        if (idx < N_NODES) g_ptr[idx + 1] = incl;
        __syncthreads();
        if (tid == 1023) carry_s = incl;
        __syncthreads();
    }
}

__global__ void cursor_kernel() {
    int i = blockIdx.x * blockDim.x + threadIdx.x;
    if (i < N_NODES) g_cursor[i] = g_ptr[i];
}

__global__ void fill_kernel(const void* __restrict__ ei) {
    int e = blockIdx.x * blockDim.x + threadIdx.x;
    if (e >= N_EDGES) return;
    int src = load_idx(ei, e);
    int dst = load_idx(ei, N_EDGES + e);
    if (dst < 0 || dst >= N_NODES || src < 0 || src >= N_NODES) return;
    int p = atomicAdd(&g_cursor[dst], 1);
    if (p >= 0 && p < N_EDGES) g_csr[p] = src;
}

// ---------------- fused layer: gather-agg -> GEMM1+ReLU -> GEMM2 -> epilogue ----------------
__global__ void __launch_bounds__(256, 1) layer_kernel(
    const float* __restrict__ x,
    const float* __restrict__ W1, const float* __restrict__ b1,
    const float* __restrict__ W2, const float* __restrict__ b2,
    const float* __restrict__ eps_arr, int layer,
    float* __restrict__ out, const void* __restrict__ batch, int last)
{
    extern __shared__ float smem[];
    float* sW1 = smem;               // 128x128
    float* sW2 = smem + 16384;       // 128x128
    float* sA  = smem + 32768;       // BM x SA_STRIDE (also reused as T tile)

    const int tid = threadIdx.x;
    const int r0 = blockIdx.x * BM;
    const float* __restrict__ hin = (layer == 0) ? x : g_h;

    // --- load weights into smem ---
    {
        const float4* w1 = (const float4*)W1;
        const float4* w2 = (const float4*)W2;
        float4* s1 = (float4*)sW1;
        float4* s2 = (float4*)sW2;
        #pragma unroll
        for (int t = 0; t < 16; t++) {
            s1[tid + t * 256] = w1[tid + t * 256];
            s2[tid + t * 256] = w2[tid + t * 256];
        }
    }

    // --- gather: agg = (1+eps)*h[r] + sum_{j->r} h[j]; warp per row ---
    {
        const int lane = tid & 31, wid = tid >> 5;
        const float ep = 1.0f + eps_arr[layer];
        const float4* __restrict__ h4 = (const float4*)hin;
        #pragma unroll
        for (int rl = wid; rl < BM; rl += 8) {
            int r = r0 + rl;
            float4 acc = make_float4(0.f, 0.f, 0.f, 0.f);
            if (r < N_NODES) {
                float4 v = h4[r * 32 + lane];
                acc.x = ep * v.x; acc.y = ep * v.y; acc.z = ep * v.z; acc.w = ep * v.w;
                int e = g_ptr[r], end = g_ptr[r + 1];
                while (e < end) {
                    int n = end - e;
                    int sidx[8];
                    #pragma unroll
                    for (int t = 0; t < 8; t++) sidx[t] = (t < n) ? g_csr[e + t] : -1;
                    #pragma unroll
                    for (int t = 0; t < 8; t++) {
                        if (sidx[t] >= 0) {
                            float4 u = h4[sidx[t] * 32 + lane];
                            acc.x += u.x; acc.y += u.y; acc.z += u.z; acc.w += u.w;
                        }
                    }
                    e += 8;
                }
            }
            *(float4*)&sA[rl * SA_STRIDE + lane * 4] = acc;
        }
    }
    __syncthreads();

    const int tx = tid & 15, ty = tid >> 4;
    const int col0 = tx * 8;

    // --- GEMM1: T = relu(A @ W1 + b1), packed f32x2 FMAs ---
    u64 acc1[4][4];
    #pragma unroll
    for (int jp = 0; jp < 4; jp++) {
        u64 bb = pack2(b1[col0 + jp * 2], b1[col0 + jp * 2 + 1]);
        #pragma unroll
        for (int i = 0; i < 4; i++) acc1[i][jp] = bb;
    }
    #pragma unroll 4
    for (int k = 0; k < 128; k++) {
        ulonglong2 bq0 = *(const ulonglong2*)&sW1[k * 128 + col0];
        ulonglong2 bq1 = *(const ulonglong2*)&sW1[k * 128 + col0 + 4];
        u64 bv0 = bq0.x, bv1 = bq0.y, bv2 = bq1.x, bv3 = bq1.y;
        #pragma unroll
        for (int i = 0; i < 4; i++) {
            float a = sA[(ty * 4 + i) * SA_STRIDE + k];
            u64 ap = pack2(a, a);
            fma2(acc1[i][0], ap, bv0);
            fma2(acc1[i][1], ap, bv1);
            fma2(acc1[i][2], ap, bv2);
            fma2(acc1[i][3], ap, bv3);
        }
    }
    __syncthreads();
    // write relu(T) into sA (aliased)
    #pragma unroll
    for (int i = 0; i < 4; i++) {
        float t[8];
        #pragma unroll
        for (int jp = 0; jp < 4; jp++) unpack2(acc1[i][jp], t[jp * 2], t[jp * 2 + 1]);
        #pragma unroll
        for (int j = 0; j < 8; j++) t[j] = fmaxf(t[j], 0.0f);
        float4* dst = (float4*)&sA[(ty * 4 + i) * SA_STRIDE + col0];
        dst[0] = make_float4(t[0], t[1], t[2], t[3]);
        dst[1] = make_float4(t[4], t[5], t[6], t[7]);
    }
    __syncthreads();

    // --- GEMM2: Z = T @ W2 + b2 ---
    u64 acc2[4][4];
    #pragma unroll
    for (int jp = 0; jp < 4; jp++) {
        u64 bb = pack2(b2[col0 + jp * 2], b2[col0 + jp * 2 + 1]);
        #pragma unroll
        for (int i = 0; i < 4; i++) acc2[i][jp] = bb;
    }
    #pragma unroll 4
    for (int k = 0; k < 128; k++) {
        ulonglong2 bq0 = *(const ulonglong2*)&sW2[k * 128 + col0];
        ulonglong2 bq1 = *(const ulonglong2*)&sW2[k * 128 + col0 + 4];
        u64 bv0 = bq0.x, bv1 = bq0.y, bv2 = bq1.x, bv3 = bq1.y;
        #pragma unroll
        for (int i = 0; i < 4; i++) {
            float a = sA[(ty * 4 + i) * SA_STRIDE + k];
            u64 ap = pack2(a, a);
            fma2(acc2[i][0], ap, bv0);
            fma2(acc2[i][1], ap, bv1);
            fma2(acc2[i][2], ap, bv2);
            fma2(acc2[i][3], ap, bv3);
        }
    }

    float zf[4][8];
    #pragma unroll
    for (int i = 0; i < 4; i++)
        #pragma unroll
        for (int jp = 0; jp < 4; jp++)
            unpack2(acc2[i][jp], zf[i][jp * 2], zf[i][jp * 2 + 1]);

    if (!last) {
        // store z + accumulate BN statistics (sum, sumsq per column)
        float* stats = &g_stats[layer * 2 * D];
        float* ssum = sW1;        // reuse; sW1 no longer read
        float* ssq  = sW1 + D;
        if (tid < 2 * D) sW1[tid] = 0.0f;
        #pragma unroll
        for (int i = 0; i < 4; i++) {
            int r = r0 + ty * 4 + i;
            if (r < N_NODES) {
                float4* zp = (float4*)&g_z[(size_t)r * D + col0];
                zp[0] = make_float4(zf[i][0], zf[i][1], zf[i][2], zf[i][3]);
                zp[1] = make_float4(zf[i][4], zf[i][5], zf[i][6], zf[i][7]);
            }
        }
        __syncthreads();
        #pragma unroll
        for (int j = 0; j < 8; j++) {
            float s = 0.0f, q = 0.0f;
            #pragma unroll
            for (int i = 0; i < 4; i++) {
                int r = r0 + ty * 4 + i;
                if (r < N_NODES) { float v = zf[i][j]; s += v; q += v * v; }
            }
            atomicAdd(&ssum[col0 + j], s);
            atomicAdd(&ssq[col0 + j], q);
        }
        __syncthreads();
        if (tid < D) {
            atomicAdd(&stats[tid], ssum[tid]);
            atomicAdd(&stats[D + tid], ssq[tid]);
        }
    } else {
        // global_add_pool: combine consecutive rows of equal graph before atomics
        #pragma unroll
        for (int j = 0; j < 8; j++) {
            int gcur = -1;
            float a = 0.0f;
            #pragma unroll
            for (int i = 0; i < 4; i++) {
                int r = r0 + ty * 4 + i;
                if (r < N_NODES) {
                    int g = load_idx(batch, r);
                    float v = zf[i][j];
                    if (g == gcur) a += v;
                    else {
                        if (gcur >= 0 && gcur < NUM_GRAPHS)
                            atomicAdd(&out[gcur * D + col0 + j], a);
                        gcur = g; a = v;
                    }
                }
            }
            if (gcur >= 0 && gcur < NUM_GRAPHS)
                atomicAdd(&out[gcur * D + col0 + j], a);
        }
    }
}

// ---------------- BatchNorm(training stats) + ReLU ----------------
__global__ void bn_kernel(const float* __restrict__ gamma,
                          const float* __restrict__ beta, int layer) {
    int idx = blockIdx.x * blockDim.x + threadIdx.x;
    if (idx >= N_NODES * (D / 4)) return;
    const float* stats = &g_stats[layer * 2 * D];
    int c0 = (idx & 31) * 4;
    float4 zv = ((const float4*)g_z)[idx];
    float zi[4] = {zv.x, zv.y, zv.z, zv.w};
    float o[4];
    const float invN = 1.0f / (float)N_NODES;
    #pragma unroll
    for (int l = 0; l < 4; l++) {
        int c = c0 + l;
        float mu = stats[c] * invN;
        float var = stats[D + c] * invN - mu * mu;
        float sc = rsqrtf(var + BN_EPS) * gamma[c];
        float v = (zi[l] - mu) * sc + beta[c];
        o[l] = fmaxf(v, 0.0f);
    }
    ((float4*)g_h)[idx] = make_float4(o[0], o[1], o[2], o[3]);
}

// ---------------- launch ----------------
extern "C" void kernel_launch(void* const* d_in, const int* in_sizes, int n_in,
                              void* d_out, int out_size) {
    const float* x     = (const float*)d_in[0];
    const void*  ei    = d_in[1];
    const void*  batch = d_in[2];
    const float* W1    = (const float*)d_in[3];
    const float* b1    = (const float*)d_in[4];
    const float* W2    = (const float*)d_in[5];
    const float* b2    = (const float*)d_in[6];
    const float* eps   = (const float*)d_in[7];
    const float* gamma = (const float*)d_in[8];
    const float* beta  = (const float*)d_in[9];
    float* out = (float*)d_out;

    cudaFuncSetAttribute(layer_kernel, cudaFuncAttributeMaxDynamicSharedMemorySize,
                         SMEM_BYTES);

    detect_kernel<<<1, 256>>>(ei);
    zero_kernel<<<64, 256>>>(out);
    hist_kernel<<<(N_EDGES + 255) / 256, 256>>>(ei);
    scan_kernel<<<1, 1024>>>();
    cursor_kernel<<<(N_NODES + 255) / 256, 256>>>();
    fill_kernel<<<(N_EDGES + 255) / 256, 256>>>(ei);

    for (int i = 0; i < N_LAYERS; i++) {
        layer_kernel<<<LAYER_GRID, 256, SMEM_BYTES>>>(
            x, W1 + i * D * D, b1 + i * D, W2 + i * D * D, b2 + i * D,
            eps, i, out, batch, (i == N_LAYERS - 1) ? 1 : 0);
        if (i < N_LAYERS - 1) {
            bn_kernel<<<(N_NODES * (D / 4) + 255) / 256, 256>>>(
                gamma + i * D, beta + i * D, i);
        }
    }
}

// round 3
// speedup vs baseline: 1.3810x; 1.3810x over previous
#include <cuda_runtime.h>

#define N_NODES 50000
#define N_EDGES 800000
#define D 128
#define NUM_GRAPHS 128
#define N_LAYERS 4
#define BN_EPS 1e-5f

#define BM 64
#define SA_STRIDE 132
#define GEMM_GRID ((N_NODES + BM - 1) / BM)
#define GEMM_SMEM ((16384 + BM * SA_STRIDE) * 4)

#define SCAN_BLK 1024
#define SCAN_NBLK ((N_NODES + SCAN_BLK - 1) / SCAN_BLK)

// ---------------- device scratch ----------------
__device__ float g_a[(size_t)N_NODES * D];
__device__ float g_z[(size_t)N_NODES * D];
__device__ int   g_deg[N_NODES];
__device__ int   g_ptr[N_NODES + 1];
__device__ int   g_cursor[N_NODES];
__device__ int   g_csr[N_EDGES];
__device__ int   g_bsum[SCAN_NBLK];
__device__ float g_stats[(N_LAYERS - 1) * 2 * D];
__device__ int   g_idx64;

typedef unsigned long long u64;

__device__ __forceinline__ u64 pack2(float lo, float hi) {
    u64 r; asm("mov.b64 %0, {%1, %2};" : "=l"(r) : "f"(lo), "f"(hi)); return r;
}
__device__ __forceinline__ void unpack2(u64 v, float& lo, float& hi) {
    asm("mov.b64 {%0, %1}, %2;" : "=f"(lo), "=f"(hi) : "l"(v));
}
__device__ __forceinline__ void fma2(u64& d, u64 a, u64 b) {
    asm("fma.rn.f32x2 %0, %1, %2, %0;" : "+l"(d) : "l"(a), "l"(b));
}
__device__ __forceinline__ int load_idx(const void* p, int i) {
    if (g_idx64) return (int)((const long long*)p)[i];
    return ((const int*)p)[i];
}

// ---------------- dtype detection ----------------
__global__ void detect_kernel(const void* ei) {
    __shared__ int any_nonzero;
    const int* a = (const int*)ei;
    if (threadIdx.x == 0) any_nonzero = 0;
    __syncthreads();
    int step = (2 * N_EDGES) / 256;
    int pos = (threadIdx.x * step) | 1;
    if (a[pos] != 0) any_nonzero = 1;
    __syncthreads();
    if (threadIdx.x == 0) g_idx64 = any_nonzero ? 0 : 1;
}

// ---------------- CSR build ----------------
__global__ void zero_kernel(float* __restrict__ out) {
    int i = blockIdx.x * blockDim.x + threadIdx.x;
    int stride = gridDim.x * blockDim.x;
    for (int t = i; t < N_NODES; t += stride) g_deg[t] = 0;
    for (int t = i; t < (N_LAYERS - 1) * 2 * D; t += stride) g_stats[t] = 0.0f;
    for (int t = i; t < NUM_GRAPHS * D; t += stride) out[t] = 0.0f;
}

__global__ void hist_kernel(const void* __restrict__ ei) {
    int e = blockIdx.x * blockDim.x + threadIdx.x;
    if (e < N_EDGES) {
        int dst = load_idx(ei, N_EDGES + e);
        if (dst >= 0 && dst < N_NODES) atomicAdd(&g_deg[dst], 1);
    }
}

__global__ void scan_part_kernel() {
    __shared__ int wsum[32];
    const int tid = threadIdx.x;
    const int lane = tid & 31, wid = tid >> 5;
    int idx = blockIdx.x * SCAN_BLK + tid;
    int v = (idx < N_NODES) ? g_deg[idx] : 0;
    int s = v;
    #pragma unroll
    for (int off = 1; off < 32; off <<= 1) {
        int t = __shfl_up_sync(0xffffffffu, s, off);
        if (lane >= off) s += t;
    }
    if (lane == 31) wsum[wid] = s;
    __syncthreads();
    if (wid == 0) {
        int ws = wsum[lane];
        #pragma unroll
        for (int off = 1; off < 32; off <<= 1) {
            int t = __shfl_up_sync(0xffffffffu, ws, off);
            if (lane >= off) ws += t;
        }
        wsum[lane] = ws;
    }
    __syncthreads();
    int incl = s + ((wid > 0) ? wsum[wid - 1] : 0);
    if (idx < N_NODES) g_ptr[idx + 1] = incl;
    if (tid == SCAN_BLK - 1) g_bsum[blockIdx.x] = incl;
}

__global__ void scan_top_kernel() {
    __shared__ int sh[SCAN_NBLK];
    int tid = threadIdx.x;
    if (tid < SCAN_NBLK) sh[tid] = g_bsum[tid];
    __syncthreads();
    if (tid == 0) {
        int run = 0;
        for (int i = 0; i < SCAN_NBLK; i++) { int t = sh[i]; sh[i] = run; run += t; }
    }
    __syncthreads();
    if (tid < SCAN_NBLK) g_bsum[tid] = sh[tid];
}

__global__ void scan_add_kernel() {
    int idx = blockIdx.x * SCAN_BLK + threadIdx.x;
    if (idx < N_NODES) {
        int p = g_ptr[idx + 1] + g_bsum[blockIdx.x];
        g_ptr[idx + 1] = p;
        g_cursor[idx + 1] = p;   // exclusive start of node idx+1
    }
    if (idx == 0) { g_ptr[0] = 0; g_cursor[0] = 0; }
}

__global__ void fill_kernel(const void* __restrict__ ei) {
    int e = blockIdx.x * blockDim.x + threadIdx.x;
    if (e >= N_EDGES) return;
    int src = load_idx(ei, e);
    int dst = load_idx(ei, N_EDGES + e);
    if (dst < 0 || dst >= N_NODES || src < 0 || src >= N_NODES) return;
    int p = atomicAdd(&g_cursor[dst], 1);
    if (p >= 0 && p < N_EDGES) g_csr[p] = src;
}

// ---------------- gather with fused BN+ReLU of previous layer ----------------
__global__ void __launch_bounds__(256) gather_kernel(
    const float* __restrict__ x, const float* __restrict__ eps_arr,
    const float* __restrict__ gamma, const float* __restrict__ beta,
    int layer)
{
    __shared__ float ssc[D], ssh[D];
    const int tid = threadIdx.x;
    const int apply_bn = (layer > 0);
    if (apply_bn && tid < D) {
        const float* stats = &g_stats[(layer - 1) * 2 * D];
        const float invN = 1.0f / (float)N_NODES;
        float mu = stats[tid] * invN;
        float var = stats[D + tid] * invN - mu * mu;
        float sc = rsqrtf(var + BN_EPS) * gamma[tid];
        ssc[tid] = sc;
        ssh[tid] = beta[tid] - mu * sc;
    }
    __syncthreads();

    const int lane = tid & 31, wid = tid >> 5;
    const int r = blockIdx.x * 8 + wid;
    if (r >= N_NODES) return;

    float4 sc4 = make_float4(1.f, 1.f, 1.f, 1.f);
    float4 sh4 = make_float4(0.f, 0.f, 0.f, 0.f);
    if (apply_bn) {
        sc4 = *(const float4*)&ssc[lane * 4];
        sh4 = *(const float4*)&ssh[lane * 4];
    }
    const float ep = 1.0f + eps_arr[layer];
    const float4* __restrict__ h4 = apply_bn ? (const float4*)g_z : (const float4*)x;

    float4 v = h4[r * 32 + lane];
    float4 acc;
    if (apply_bn) {
        acc.x = ep * fmaxf(v.x * sc4.x + sh4.x, 0.0f);
        acc.y = ep * fmaxf(v.y * sc4.y + sh4.y, 0.0f);
        acc.z = ep * fmaxf(v.z * sc4.z + sh4.z, 0.0f);
        acc.w = ep * fmaxf(v.w * sc4.w + sh4.w, 0.0f);
    } else {
        acc.x = ep * v.x; acc.y = ep * v.y; acc.z = ep * v.z; acc.w = ep * v.w;
    }

    int e = g_ptr[r], end = g_ptr[r + 1];
    while (e < end) {
        int n = end - e;
        int sidx[8];
        #pragma unroll
        for (int t = 0; t < 8; t++) sidx[t] = (t < n) ? g_csr[e + t] : -1;
        #pragma unroll
        for (int t = 0; t < 8; t++) {
            if (sidx[t] >= 0) {
                float4 u = h4[sidx[t] * 32 + lane];
                if (apply_bn) {
                    acc.x += fmaxf(u.x * sc4.x + sh4.x, 0.0f);
                    acc.y += fmaxf(u.y * sc4.y + sh4.y, 0.0f);
                    acc.z += fmaxf(u.z * sc4.z + sh4.z, 0.0f);
                    acc.w += fmaxf(u.w * sc4.w + sh4.w, 0.0f);
                } else {
                    acc.x += u.x; acc.y += u.y; acc.z += u.z; acc.w += u.w;
                }
            }
        }
        e += 8;
    }
    ((float4*)g_a)[r * 32 + lane] = acc;
}

// ---------------- GEMM: Z = relu(A@W1+b1)@W2 + b2, epilogue stats/pool ----------------
__global__ void __launch_bounds__(256, 2) gemm_kernel(
    const float* __restrict__ W1, const float* __restrict__ b1,
    const float* __restrict__ W2, const float* __restrict__ b2,
    int layer, float* __restrict__ out, const void* __restrict__ batch, int last)
{
    extern __shared__ float smem[];
    float* sW = smem;
    float* sA = smem + 16384;

    const int tid = threadIdx.x;
    const int r0 = blockIdx.x * BM;

    {
        const float4* w1 = (const float4*)W1;
        float4* s1 = (float4*)sW;
        #pragma unroll
        for (int t = 0; t < 16; t++) s1[tid + t * 256] = w1[tid + t * 256];

        const float4* a4 = (const float4*)g_a;
        #pragma unroll
        for (int t = 0; t < 8; t++) {
            int g = tid + t * 256;
            int row = g >> 5, col = g & 31;
            float4 v = make_float4(0.f, 0.f, 0.f, 0.f);
            if (r0 + row < N_NODES) v = a4[(r0 + row) * 32 + col];
            *(float4*)&sA[row * SA_STRIDE + col * 4] = v;
        }
    }
    __syncthreads();

    const int tx = tid & 15, ty = tid >> 4;
    const int col0 = tx * 8;

    u64 acc1[4][4];
    #pragma unroll
    for (int jp = 0; jp < 4; jp++) {
        u64 bb = pack2(b1[col0 + jp * 2], b1[col0 + jp * 2 + 1]);
        #pragma unroll
        for (int i = 0; i < 4; i++) acc1[i][jp] = bb;
    }
    #pragma unroll 4
    for (int k = 0; k < 128; k++) {
        ulonglong2 bq0 = *(const ulonglong2*)&sW[k * 128 + col0];
        ulonglong2 bq1 = *(const ulonglong2*)&sW[k * 128 + col0 + 4];
        u64 bv0 = bq0.x, bv1 = bq0.y, bv2 = bq1.x, bv3 = bq1.y;
        #pragma unroll
        for (int i = 0; i < 4; i++) {
            float a = sA[(ty * 4 + i) * SA_STRIDE + k];
            u64 ap = pack2(a, a);
            fma2(acc1[i][0], ap, bv0);
            fma2(acc1[i][1], ap, bv1);
            fma2(acc1[i][2], ap, bv2);
            fma2(acc1[i][3], ap, bv3);
        }
    }
    __syncthreads();

    #pragma unroll
    for (int i = 0; i < 4; i++) {
        float t[8];
        #pragma unroll
        for (int jp = 0; jp < 4; jp++) unpack2(acc1[i][jp], t[jp * 2], t[jp * 2 + 1]);
        #pragma unroll
        for (int j = 0; j < 8; j++) t[j] = fmaxf(t[j], 0.0f);
        float4* dst = (float4*)&sA[(ty * 4 + i) * SA_STRIDE + col0];
        dst[0] = make_float4(t[0], t[1], t[2], t[3]);
        dst[1] = make_float4(t[4], t[5], t[6], t[7]);
    }
    {
        const float4* w2 = (const float4*)W2;
        float4* s2 = (float4*)sW;
        #pragma unroll
        for (int t = 0; t < 16; t++) s2[tid + t * 256] = w2[tid + t * 256];
    }
    __syncthreads();

    u64 acc2[4][4];
    #pragma unroll
    for (int jp = 0; jp < 4; jp++) {
        u64 bb = pack2(b2[col0 + jp * 2], b2[col0 + jp * 2 + 1]);
        #pragma unroll
        for (int i = 0; i < 4; i++) acc2[i][jp] = bb;
    }
    #pragma unroll 4
    for (int k = 0; k < 128; k++) {
        ulonglong2 bq0 = *(const ulonglong2*)&sW[k * 128 + col0];
        ulonglong2 bq1 = *(const ulonglong2*)&sW[k * 128 + col0 + 4];
        u64 bv0 = bq0.x, bv1 = bq0.y, bv2 = bq1.x, bv3 = bq1.y;
        #pragma unroll
        for (int i = 0; i < 4; i++) {
            float a = sA[(ty * 4 + i) * SA_STRIDE + k];
            u64 ap = pack2(a, a);
            fma2(acc2[i][0], ap, bv0);
            fma2(acc2[i][1], ap, bv1);
            fma2(acc2[i][2], ap, bv2);
            fma2(acc2[i][3], ap, bv3);
        }
    }

    float zf[4][8];
    #pragma unroll
    for (int i = 0; i < 4; i++)
        #pragma unroll
        for (int jp = 0; jp < 4; jp++)
            unpack2(acc2[i][jp], zf[i][jp * 2], zf[i][jp * 2 + 1]);

    if (!last) {
        float* stats = &g_stats[layer * 2 * D];
        float* ssum = sW;
        float* ssq  = sW + D;
        if (tid < 2 * D) sW[tid] = 0.0f;
        #pragma unroll
        for (int i = 0; i < 4; i++) {
            int r = r0 + ty * 4 + i;
            if (r < N_NODES) {
                float4* zp = (float4*)&g_z[(size_t)r * D + col0];
                zp[0] = make_float4(zf[i][0], zf[i][1], zf[i][2], zf[i][3]);
                zp[1] = make_float4(zf[i][4], zf[i][5], zf[i][6], zf[i][7]);
            }
        }
        __syncthreads();
        #pragma unroll
        for (int j = 0; j < 8; j++) {
            float s = 0.0f, q = 0.0f;
            #pragma unroll
            for (int i = 0; i < 4; i++) {
                int r = r0 + ty * 4 + i;
                if (r < N_NODES) { float v = zf[i][j]; s += v; q += v * v; }
            }
            atomicAdd(&ssum[col0 + j], s);
            atomicAdd(&ssq[col0 + j], q);
        }
        __syncthreads();
        if (tid < D) {
            atomicAdd(&stats[tid], ssum[tid]);
            atomicAdd(&stats[D + tid], ssq[tid]);
        }
    } else {
        #pragma unroll
        for (int j = 0; j < 8; j++) {
            int gcur = -1;
            float a = 0.0f;
            #pragma unroll
            for (int i = 0; i < 4; i++) {
                int r = r0 + ty * 4 + i;
                if (r < N_NODES) {
                    int g = load_idx(batch, r);
                    float v = zf[i][j];
                    if (g == gcur) a += v;
                    else {
                        if (gcur >= 0 && gcur < NUM_GRAPHS)
                            atomicAdd(&out[gcur * D + col0 + j], a);
                        gcur = g; a = v;
                    }
                }
            }
            if (gcur >= 0 && gcur < NUM_GRAPHS)
                atomicAdd(&out[gcur * D + col0 + j], a);
        }
    }
}

// ---------------- launch ----------------
extern "C" void kernel_launch(void* const* d_in, const int* in_sizes, int n_in,
                              void* d_out, int out_size) {
    const float* x     = (const float*)d_in[0];
    const void*  ei    = d_in[1];
    const void*  batch = d_in[2];
    const float* W1    = (const float*)d_in[3];
    const float* b1    = (const float*)d_in[4];
    const float* W2    = (const float*)d_in[5];
    const float* b2    = (const float*)d_in[6];
    const float* eps   = (const float*)d_in[7];
    const float* gamma = (const float*)d_in[8];
    const float* beta  = (const float*)d_in[9];
    float* out = (float*)d_out;

    cudaFuncSetAttribute(gemm_kernel, cudaFuncAttributeMaxDynamicSharedMemorySize,
                         GEMM_SMEM);

    detect_kernel<<<1, 256>>>(ei);
    zero_kernel<<<64, 256>>>(out);
    hist_kernel<<<(N_EDGES + 255) / 256, 256>>>(ei);
    scan_part_kernel<<<SCAN_NBLK, SCAN_BLK>>>();
    scan_top_kernel<<<1, 64>>>();
    scan_add_kernel<<<SCAN_NBLK, SCAN_BLK>>>();
    fill_kernel<<<(N_EDGES + 255) / 256, 256>>>(ei);

    for (int i = 0; i < N_LAYERS; i++) {
        gather_kernel<<<(N_NODES + 7) / 8, 256>>>(
            x, eps, gamma + (i > 0 ? (i - 1) * D : 0),
            beta + (i > 0 ? (i - 1) * D : 0), i);
        gemm_kernel<<<GEMM_GRID, 256, GEMM_SMEM>>>(
            W1 + i * D * D, b1 + i * D, W2 + i * D * D, b2 + i * D,
            i, out, batch, (i == N_LAYERS - 1) ? 1 : 0);
    }
}

// round 5
// speedup vs baseline: 2.1193x; 1.5346x over previous
#include <cuda_runtime.h>
#include <cstdint>

#define N_NODES 50000
#define N_EDGES 800000
#define D 128
#define NUM_GRAPHS 128
#define N_LAYERS 4
#define BN_EPS 1e-5f

#define MT 128
#define GEMM_GRID ((N_NODES + MT - 1) / MT)

#define SCAN_BLK 1024
#define SCAN_NBLK ((N_NODES + SCAN_BLK - 1) / SCAN_BLK)

// ---- smem float-index map for gemm_mma ----
#define SB1   0
#define SB2   128
#define SSUM  256
#define SSQ   384
#define SA    512                 // 128 x 132 fp32 (A tile / T tile / Z staging)
#define SWH   (SA + 128 * 132)    // 128 x 132 u32 (W hi)
#define SWL   (SWH + 128 * 132)   // 128 x 132 u32 (W lo)
#define SM_FLOATS (SWL + 128 * 132)
#define SM_BYTES (SM_FLOATS * 4)  // 204800

// ---------------- device scratch ----------------
__device__ float g_a[(size_t)N_NODES * D];
__device__ float g_z[(size_t)N_NODES * D];
__device__ int   g_deg[N_NODES];
__device__ int   g_ptr[N_NODES + 1];
__device__ int   g_cursor[N_NODES];
__device__ int   g_csr[N_EDGES];
__device__ int   g_bsum[SCAN_NBLK];
__device__ float g_stats[(N_LAYERS - 1) * 2 * D];
__device__ int   g_idx64;

__device__ __forceinline__ int load_idx(const void* p, int i) {
    if (g_idx64) return (int)((const long long*)p)[i];
    return ((const int*)p)[i];
}

__device__ __forceinline__ void cvt_hilo(float v, uint32_t& hi, uint32_t& lo) {
    asm("cvt.rna.tf32.f32 %0, %1;" : "=r"(hi) : "f"(v));
    float l = v - __uint_as_float(hi);
    asm("cvt.rna.tf32.f32 %0, %1;" : "=r"(lo) : "f"(l));
}

__device__ __forceinline__ void mma8(float* c, uint32_t a0, uint32_t a1,
                                     uint32_t a2, uint32_t a3,
                                     uint32_t b0, uint32_t b1) {
    asm volatile(
        "mma.sync.aligned.m16n8k8.row.col.f32.tf32.tf32.f32 "
        "{%0,%1,%2,%3}, {%4,%5,%6,%7}, {%8,%9}, {%0,%1,%2,%3};"
        : "+f"(c[0]), "+f"(c[1]), "+f"(c[2]), "+f"(c[3])
        : "r"(a0), "r"(a1), "r"(a2), "r"(a3), "r"(b0), "r"(b1));
}

// ---------------- dtype detection ----------------
__global__ void detect_kernel(const void* ei) {
    __shared__ int any_nonzero;
    const int* a = (const int*)ei;
    if (threadIdx.x == 0) any_nonzero = 0;
    __syncthreads();
    int step = (2 * N_EDGES) / 256;
    int pos = (threadIdx.x * step) | 1;
    if (a[pos] != 0) any_nonzero = 1;
    __syncthreads();
    if (threadIdx.x == 0) g_idx64 = any_nonzero ? 0 : 1;
}

// ---------------- CSR build ----------------
__global__ void zero_kernel(float* __restrict__ out) {
    int i = blockIdx.x * blockDim.x + threadIdx.x;
    int stride = gridDim.x * blockDim.x;
    for (int t = i; t < N_NODES; t += stride) g_deg[t] = 0;
    for (int t = i; t < (N_LAYERS - 1) * 2 * D; t += stride) g_stats[t] = 0.0f;
    for (int t = i; t < NUM_GRAPHS * D; t += stride) out[t] = 0.0f;
}

__global__ void hist_kernel(const void* __restrict__ ei) {
    int e = blockIdx.x * blockDim.x + threadIdx.x;
    if (e < N_EDGES) {
        int dst = load_idx(ei, N_EDGES + e);
        if (dst >= 0 && dst < N_NODES) atomicAdd(&g_deg[dst], 1);
    }
}

__global__ void scan_part_kernel() {
    __shared__ int wsum[32];
    const int tid = threadIdx.x;
    const int lane = tid & 31, wid = tid >> 5;
    int idx = blockIdx.x * SCAN_BLK + tid;
    int v = (idx < N_NODES) ? g_deg[idx] : 0;
    int s = v;
    #pragma unroll
    for (int off = 1; off < 32; off <<= 1) {
        int t = __shfl_up_sync(0xffffffffu, s, off);
        if (lane >= off) s += t;
    }
    if (lane == 31) wsum[wid] = s;
    __syncthreads();
    if (wid == 0) {
        int ws = wsum[lane];
        #pragma unroll
        for (int off = 1; off < 32; off <<= 1) {
            int t = __shfl_up_sync(0xffffffffu, ws, off);
            if (lane >= off) ws += t;
        }
        wsum[lane] = ws;
    }
    __syncthreads();
    int incl = s + ((wid > 0) ? wsum[wid - 1] : 0);
    if (idx < N_NODES) g_ptr[idx + 1] = incl;
    if (tid == SCAN_BLK - 1) g_bsum[blockIdx.x] = incl;
}

__global__ void scan_top_kernel() {
    __shared__ int sh[SCAN_NBLK];
    int tid = threadIdx.x;
    if (tid < SCAN_NBLK) sh[tid] = g_bsum[tid];
    __syncthreads();
    if (tid == 0) {
        int run = 0;
        for (int i = 0; i < SCAN_NBLK; i++) { int t = sh[i]; sh[i] = run; run += t; }
    }
    __syncthreads();
    if (tid < SCAN_NBLK) g_bsum[tid] = sh[tid];
}

__global__ void scan_add_kernel() {
    int idx = blockIdx.x * SCAN_BLK + threadIdx.x;
    if (idx < N_NODES) {
        int p = g_ptr[idx + 1] + g_bsum[blockIdx.x];
        g_ptr[idx + 1] = p;
        g_cursor[idx + 1] = p;
    }
    if (idx == 0) { g_ptr[0] = 0; g_cursor[0] = 0; }
}

__global__ void fill_kernel(const void* __restrict__ ei) {
    int e = blockIdx.x * blockDim.x + threadIdx.x;
    if (e >= N_EDGES) return;
    int src = load_idx(ei, e);
    int dst = load_idx(ei, N_EDGES + e);
    if (dst < 0 || dst >= N_NODES || src < 0 || src >= N_NODES) return;
    int p = atomicAdd(&g_cursor[dst], 1);
    if (p >= 0 && p < N_EDGES) g_csr[p] = src;
}

// ---------------- gather with fused BN+ReLU of previous layer ----------------
__global__ void __launch_bounds__(256) gather_kernel(
    const float* __restrict__ x, const float* __restrict__ eps_arr,
    const float* __restrict__ gamma, const float* __restrict__ beta,
    int layer)
{
    __shared__ float ssc[D], ssh[D];
    const int tid = threadIdx.x;
    const int apply_bn = (layer > 0);
    if (apply_bn && tid < D) {
        const float* stats = &g_stats[(layer - 1) * 2 * D];
        const float invN = 1.0f / (float)N_NODES;
        float mu = stats[tid] * invN;
        float var = stats[D + tid] * invN - mu * mu;
        float sc = rsqrtf(var + BN_EPS) * gamma[tid];
        ssc[tid] = sc;
        ssh[tid] = beta[tid] - mu * sc;
    }
    __syncthreads();

    const int lane = tid & 31, wid = tid >> 5;
    const int r = blockIdx.x * 8 + wid;
    if (r >= N_NODES) return;

    float4 sc4 = make_float4(1.f, 1.f, 1.f, 1.f);
    float4 sh4 = make_float4(0.f, 0.f, 0.f, 0.f);
    if (apply_bn) {
        sc4 = *(const float4*)&ssc[lane * 4];
        sh4 = *(const float4*)&ssh[lane * 4];
    }
    const float ep = 1.0f + eps_arr[layer];
    const float4* __restrict__ h4 = apply_bn ? (const float4*)g_z : (const float4*)x;

    float4 v = h4[r * 32 + lane];
    float4 acc;
    if (apply_bn) {
        acc.x = ep * fmaxf(v.x * sc4.x + sh4.x, 0.0f);
        acc.y = ep * fmaxf(v.y * sc4.y + sh4.y, 0.0f);
        acc.z = ep * fmaxf(v.z * sc4.z + sh4.z, 0.0f);
        acc.w = ep * fmaxf(v.w * sc4.w + sh4.w, 0.0f);
    } else {
        acc.x = ep * v.x; acc.y = ep * v.y; acc.z = ep * v.z; acc.w = ep * v.w;
    }

    int e = g_ptr[r], end = g_ptr[r + 1];
    while (e < end) {
        int n = end - e;
        int sidx[8];
        #pragma unroll
        for (int t = 0; t < 8; t++) sidx[t] = (t < n) ? g_csr[e + t] : -1;
        #pragma unroll
        for (int t = 0; t < 8; t++) {
            if (sidx[t] >= 0) {
                float4 u = h4[sidx[t] * 32 + lane];
                if (apply_bn) {
                    acc.x += fmaxf(u.x * sc4.x + sh4.x, 0.0f);
                    acc.y += fmaxf(u.y * sc4.y + sh4.y, 0.0f);
                    acc.z += fmaxf(u.z * sc4.z + sh4.z, 0.0f);
                    acc.w += fmaxf(u.w * sc4.w + sh4.w, 0.0f);
                } else {
                    acc.x += u.x; acc.y += u.y; acc.z += u.z; acc.w += u.w;
                }
            }
        }
        e += 8;
    }
    ((float4*)g_a)[r * 32 + lane] = acc;
}

// ---------------- one 128x128x128 GEMM pass (3xTF32, acc += sA @ W) ----------------
__device__ __forceinline__ void gemm_pass(
    const float* __restrict__ smf, float (&acc)[4][4][4],
    int wr, int wc, int g, int t)
{
    const uint32_t* __restrict__ wh = (const uint32_t*)smf + SWH;
    const uint32_t* __restrict__ wl = (const uint32_t*)smf + SWL;
    #pragma unroll 1
    for (int ks = 0; ks < 16; ks++) {
        const int k0 = ks * 8;
        uint32_t ahi[4][4], alo[4][4];
        #pragma unroll
        for (int i = 0; i < 4; i++) {
            int rb = SA + (wr + i * 16 + g) * 132 + k0 + t;
            float v0 = smf[rb];
            float v1 = smf[rb + 8 * 132];
            float v2 = smf[rb + 4];
            float v3 = smf[rb + 8 * 132 + 4];
            cvt_hilo(v0, ahi[i][0], alo[i][0]);
            cvt_hilo(v1, ahi[i][1], alo[i][1]);
            cvt_hilo(v2, ahi[i][2], alo[i][2]);
            cvt_hilo(v3, ahi[i][3], alo[i][3]);
        }
        #pragma unroll
        for (int j = 0; j < 4; j++) {
            int nb = (k0 + t) * 132 + wc + j * 8 + g;
            uint32_t bh0 = wh[nb], bh1 = wh[nb + 4 * 132];
            uint32_t bl0 = wl[nb], bl1 = wl[nb + 4 * 132];
            #pragma unroll
            for (int i = 0; i < 4; i++) {
                mma8(acc[i][j], ahi[i][0], ahi[i][1], ahi[i][2], ahi[i][3], bh0, bh1);
                mma8(acc[i][j], ahi[i][0], ahi[i][1], ahi[i][2], ahi[i][3], bl0, bl1);
                mma8(acc[i][j], alo[i][0], alo[i][1], alo[i][2], alo[i][3], bh0, bh1);
            }
        }
    }
}

__device__ __forceinline__ void load_w_split(
    float* smf, const float* __restrict__ Wg, int tid)
{
    uint32_t* wh = (uint32_t*)smf + SWH;
    uint32_t* wl = (uint32_t*)smf + SWL;
    #pragma unroll
    for (int it = 0; it < 64; it++) {
        int idx = tid + it * 256;       // 16384 elems
        int k = idx >> 7, n = idx & 127;
        uint32_t hi, lo;
        cvt_hilo(Wg[idx], hi, lo);
        wh[k * 132 + n] = hi;
        wl[k * 132 + n] = lo;
    }
}

// ---------------- GEMM kernel: Z = relu(A@W1+b1)@W2 + b2 + epilogue ----------------
__global__ void __launch_bounds__(256, 1) gemm_mma(
    const float* __restrict__ W1, const float* __restrict__ b1,
    const float* __restrict__ W2, const float* __restrict__ b2,
    int layer, float* __restrict__ out, const void* __restrict__ batch, int last)
{
    extern __shared__ float smf[];
    const int tid = threadIdx.x;
    const int wid = tid >> 5, lane = tid & 31;
    const int g = lane >> 2, t = lane & 3;
    const int wr = (wid >> 2) * 64;      // warp row origin
    const int wc = (wid & 3) * 32;       // warp col origin
    const int r0 = blockIdx.x * MT;

    if (tid < 128) {
        smf[SB1 + tid] = b1[tid];
        smf[SB2 + tid] = b2[tid];
        smf[SSUM + tid] = 0.0f;
        smf[SSQ + tid] = 0.0f;
    }

    // fill A tile (fp32) from g_a
    {
        const float4* a4 = (const float4*)g_a;
        #pragma unroll
        for (int it = 0; it < 16; it++) {
            int idx = tid + it * 256;       // 4096 float4
            int m = idx >> 5, kq = idx & 31;
            float4 v = make_float4(0.f, 0.f, 0.f, 0.f);
            if (r0 + m < N_NODES) v = a4[(size_t)(r0 + m) * 32 + kq];
            *(float4*)&smf[SA + m * 132 + kq * 4] = v;
        }
    }
    load_w_split(smf, W1, tid);
    __syncthreads();

    float acc[4][4][4];
    #pragma unroll
    for (int i = 0; i < 4; i++)
        #pragma unroll
        for (int j = 0; j < 4; j++)
            #pragma unroll
            for (int c = 0; c < 4; c++) acc[i][j][c] = 0.0f;

    gemm_pass(smf, acc, wr, wc, g, t);
    __syncthreads();

    // T = relu(acc + b1) -> sA; load W2
    #pragma unroll
    for (int i = 0; i < 4; i++) {
        #pragma unroll
        for (int j = 0; j < 4; j++) {
            int c0 = wc + j * 8 + 2 * t;
            int rA = wr + i * 16 + g;
            float bb0 = smf[SB1 + c0], bb1 = smf[SB1 + c0 + 1];
            float2 u0 = make_float2(fmaxf(acc[i][j][0] + bb0, 0.0f),
                                    fmaxf(acc[i][j][1] + bb1, 0.0f));
            float2 u1 = make_float2(fmaxf(acc[i][j][2] + bb0, 0.0f),
                                    fmaxf(acc[i][j][3] + bb1, 0.0f));
            *(float2*)&smf[SA + rA * 132 + c0] = u0;
            *(float2*)&smf[SA + (rA + 8) * 132 + c0] = u1;
        }
    }
    load_w_split(smf, W2, tid);
    __syncthreads();

    #pragma unroll
    for (int i = 0; i < 4; i++)
        #pragma unroll
        for (int j = 0; j < 4; j++)
            #pragma unroll
            for (int c = 0; c < 4; c++) acc[i][j][c] = 0.0f;

    gemm_pass(smf, acc, wr, wc, g, t);
    __syncthreads();

    // stage z = acc + b2 into sA
    #pragma unroll
    for (int i = 0; i < 4; i++) {
        #pragma unroll
        for (int j = 0; j < 4; j++) {
            int c0 = wc + j * 8 + 2 * t;
            int rA = wr + i * 16 + g;
            float bb0 = smf[SB2 + c0], bb1 = smf[SB2 + c0 + 1];
            float2 u0 = make_float2(acc[i][j][0] + bb0, acc[i][j][1] + bb1);
            float2 u1 = make_float2(acc[i][j][2] + bb0, acc[i][j][3] + bb1);
            *(float2*)&smf[SA + rA * 132 + c0] = u0;
            *(float2*)&smf[SA + (rA + 8) * 132 + c0] = u1;
        }
    }
    __syncthreads();

    const int col4 = tid & 31;
    if (!last) {
        float s[4] = {0, 0, 0, 0}, q[4] = {0, 0, 0, 0};
        #pragma unroll
        for (int it = 0; it < 16; it++) {
            int row = (tid >> 5) + it * 8;
            int r = r0 + row;
            if (r < N_NODES) {
                float4 z4 = *(const float4*)&smf[SA + row * 132 + col4 * 4];
                *(float4*)&g_z[(size_t)r * D + col4 * 4] = z4;
                s[0] += z4.x; q[0] += z4.x * z4.x;
                s[1] += z4.y; q[1] += z4.y * z4.y;
                s[2] += z4.z; q[2] += z4.z * z4.z;
                s[3] += z4.w; q[3] += z4.w * z4.w;
            }
        }
        #pragma unroll
        for (int j = 0; j < 4; j++) {
            atomicAdd(&smf[SSUM + col4 * 4 + j], s[j]);
            atomicAdd(&smf[SSQ + col4 * 4 + j], q[j]);
        }
        __syncthreads();
        if (tid < 128) {
            atomicAdd(&g_stats[layer * 2 * D + tid], smf[SSUM + tid]);
            atomicAdd(&g_stats[layer * 2 * D + D + tid], smf[SSQ + tid]);
        }
    } else {
        int gcur = -1;
        float a0 = 0, a1 = 0, a2 = 0, a3 = 0;
        #pragma unroll 1
        for (int it = 0; it < 16; it++) {
            int row = (tid >> 5) + it * 8;
            int r = r0 + row;
            if (r < N_NODES) {
                float4 z4 = *(const float4*)&smf[SA + row * 132 + col4 * 4];
                int gg = load_idx(batch, r);
                if (gg == gcur) {
                    a0 += z4.x; a1 += z4.y; a2 += z4.z; a3 += z4.w;
                } else {
                    if (gcur >= 0 && gcur < NUM_GRAPHS) {
                        atomicAdd(&out[gcur * D + col4 * 4 + 0], a0);
                        atomicAdd(&out[gcur * D + col4 * 4 + 1], a1);
                        atomicAdd(&out[gcur * D + col4 * 4 + 2], a2);
                        atomicAdd(&out[gcur * D + col4 * 4 + 3], a3);
                    }
                    gcur = gg; a0 = z4.x; a1 = z4.y; a2 = z4.z; a3 = z4.w;
                }
            }
        }
        if (gcur >= 0 && gcur < NUM_GRAPHS) {
            atomicAdd(&out[gcur * D + col4 * 4 + 0], a0);
            atomicAdd(&out[gcur * D + col4 * 4 + 1], a1);
            atomicAdd(&out[gcur * D + col4 * 4 + 2], a2);
            atomicAdd(&out[gcur * D + col4 * 4 + 3], a3);
        }
    }
}

// ---------------- launch ----------------
extern "C" void kernel_launch(void* const* d_in, const int* in_sizes, int n_in,
                              void* d_out, int out_size) {
    const float* x     = (const float*)d_in[0];
    const void*  ei    = d_in[1];
    const void*  batch = d_in[2];
    const float* W1    = (const float*)d_in[3];
    const float* b1    = (const float*)d_in[4];
    const float* W2    = (const float*)d_in[5];
    const float* b2    = (const float*)d_in[6];
    const float* eps   = (const float*)d_in[7];
    const float* gamma = (const float*)d_in[8];
    const float* beta  = (const float*)d_in[9];
    float* out = (float*)d_out;

    cudaFuncSetAttribute(gemm_mma, cudaFuncAttributeMaxDynamicSharedMemorySize,
                         SM_BYTES);

    detect_kernel<<<1, 256>>>(ei);
    zero_kernel<<<64, 256>>>(out);
    hist_kernel<<<(N_EDGES + 255) / 256, 256>>>(ei);
    scan_part_kernel<<<SCAN_NBLK, SCAN_BLK>>>();
    scan_top_kernel<<<1, 64>>>();
    scan_add_kernel<<<SCAN_NBLK, SCAN_BLK>>>();
    fill_kernel<<<(N_EDGES + 255) / 256, 256>>>(ei);

    for (int i = 0; i < N_LAYERS; i++) {
        gather_kernel<<<(N_NODES + 7) / 8, 256>>>(
            x, eps, gamma + (i > 0 ? (i - 1) * D : 0),
            beta + (i > 0 ? (i - 1) * D : 0), i);
        gemm_mma<<<GEMM_GRID, 256, SM_BYTES>>>(
            W1 + i * D * D, b1 + i * D, W2 + i * D * D, b2 + i * D,
            i, out, batch, (i == N_LAYERS - 1) ? 1 : 0);
    }
}